// round 5
// baseline (speedup 1.0000x reference)
#include <cuda_runtime.h>

#define BSZ  2048
#define SEQL 50
#define NP   (BSZ*SEQL)      /* 102400 pairs */
#define ATTD 64
#define HIDD 128
#define G4   512             /* 4*HID gates */
#define FIN  19              /* 6 + 4 + 9 fused input dim */

typedef unsigned long long ull;

/* ---------------- device scratch (no cudaMalloc allowed) ---------------- */
__device__ float  g_ctx[(size_t)NP * ATTD];        /* [s][b][64]  26 MB  */
__device__ float  g_xg [(size_t)NP * G4];          /* [s][b][512] 210 MB */
__device__ float4 g_whh4t[(HIDD/4) * G4];          /* [kq][col] packed W_hh^T */

/* ---------------- f32x2 helpers (2 MACs / instr on sm_103a) ------------- */
__device__ __forceinline__ void fma2(ull& d, ull a, ull b){
    asm("fma.rn.f32x2 %0, %1, %2, %0;" : "+l"(d) : "l"(a), "l"(b));
}
__device__ __forceinline__ float2 unpk(ull v){
    float2 r; asm("mov.b64 {%0, %1}, %2;" : "=f"(r.x), "=f"(r.y) : "l"(v)); return r;
}
__device__ __forceinline__ float hsum2(ull v){ float2 f = unpk(v); return f.x + f.y; }
__device__ __forceinline__ float sigm(float x){ return 1.f/(1.f + __expf(-x)); }
__device__ __forceinline__ float tanhfast(float x){ return 1.f - 2.f/(__expf(2.f*x) + 1.f); }

/* ============ kernel 0: transpose+pack W_hh -> [kq][col] float4 ========= */
__global__ void k_pack(const float* __restrict__ Whh){
    int t = threadIdx.x, kq = blockIdx.x;             /* <<<32,512>>> */
    g_whh4t[kq*G4 + t] = make_float4(Whh[t*HIDD + 4*kq],   Whh[t*HIDD + 4*kq+1],
                                     Whh[t*HIDD + 4*kq+2], Whh[t*HIDD + 4*kq+3]);
}

/* ============ kernel 1: fused edge-MLP + 4-head attention -> ctx ========
 * 2 x 64-thread groups; thread = output channel o. Q/V weights float4-
 * packed over k (16B lane stride = conflict-free); edge rows broadcast
 * LDS.128. 11 loads per 36 fma2.                                          */
__global__ void __launch_bounds__(128) k_ctx(
    const float* __restrict__ seqs, const float* __restrict__ ets, const int* __restrict__ masks,
    const float* __restrict__ Wfus, const float* __restrict__ bfus,
    const float* __restrict__ Wk,   const float* __restrict__ bk,
    const float* __restrict__ Wq,   const float* __restrict__ bq,
    const float* __restrict__ Wv,   const float* __restrict__ bv)
{
    __shared__ __align__(16) float  s_fus[FIN*64];     /* [k][o] */
    __shared__ __align__(16) float4 s_wq4[16*64];      /* [kq][o] 4-k packed */
    __shared__ __align__(16) float4 s_wv4[16*64];
    __shared__ __align__(16) float  s_wk[6*64];
    __shared__ float s_bq[64], s_bv[64], s_bfus[64], s_bk[64];
    __shared__ __align__(16) float  s_edge[2][9*64];
    __shared__ __align__(16) float  s_raw[2][90];
    __shared__ int s_msk[2][9];

    const int tid = threadIdx.x;
    for (int i = tid; i < FIN*64; i += 128){ int k=i>>6, o=i&63; s_fus[i] = Wfus[o*FIN + k]; }
    for (int i = tid; i < 16*64; i += 128){
        int kq=i>>6, o=i&63;
        s_wq4[i] = make_float4(Wq[o*64+4*kq], Wq[o*64+4*kq+1], Wq[o*64+4*kq+2], Wq[o*64+4*kq+3]);
        s_wv4[i] = make_float4(Wv[o*64+4*kq], Wv[o*64+4*kq+1], Wv[o*64+4*kq+2], Wv[o*64+4*kq+3]);
    }
    for (int i = tid; i < 6*64; i += 128){ int k=i>>6, o=i&63; s_wk[i] = Wk[o*6 + k]; }
    if (tid < 64){ s_bq[tid]=bq[tid]; s_bv[tid]=bv[tid]; s_bfus[tid]=bfus[tid]; s_bk[tid]=bk[tid]; }
    __syncthreads();

    const int g   = tid >> 6;
    const int o   = tid & 63;
    const int bar = g + 1;                 /* named barrier id, 64 threads */
    const int ggid    = blockIdx.x*2 + g;
    const int ngroups = gridDim.x*2;

    for (int p = ggid; p < NP; p += ngroups){
        const float* sq = seqs + (size_t)p*54;
        const float* se = ets  + (size_t)p*36;
        for (int i = o; i < 90; i += 64) s_raw[g][i] = (i < 54) ? sq[i] : se[i-54];
        if (o < 9) s_msk[g][o] = masks[(size_t)p*9 + o];
        asm volatile("bar.sync %0, 64;" :: "r"(bar) : "memory");

        /* edge_info[n][o] = [seq(6),etype(4),onehot9] @ Wfus^T + bfus */
        float keyo;
        #pragma unroll
        for (int n = 0; n < 9; n++){
            float acc = s_bfus[o] + s_fus[(10+n)*64 + o];     /* one-hot loc */
            #pragma unroll
            for (int k = 0; k < 6; k++) acc += s_fus[k*64+o]     * s_raw[g][n*6+k];
            #pragma unroll
            for (int k = 0; k < 4; k++) acc += s_fus[(6+k)*64+o] * s_raw[g][54 + n*4 + k];
            s_edge[g][n*64 + o] = acc;
        }
        {   /* key from self (center cell n=4) */
            float acck = s_bk[o];
            #pragma unroll
            for (int k = 0; k < 6; k++) acck += s_wk[k*64+o] * s_raw[g][24 + k];
            keyo = acck;
        }
        asm volatile("bar.sync %0, 64;" :: "r"(bar) : "memory");

        /* Q,V: 9 slots x 64 cols, 4-k quads */
        ull q2[9], v2[9];
        #pragma unroll
        for (int n = 0; n < 9; n++){ q2[n] = 0ULL; v2[n] = 0ULL; }
        #pragma unroll 4
        for (int kq = 0; kq < 16; kq++){
            ulonglong2 wq = *reinterpret_cast<const ulonglong2*>(&s_wq4[kq*64 + o]);
            ulonglong2 wv = *reinterpret_cast<const ulonglong2*>(&s_wv4[kq*64 + o]);
            #pragma unroll
            for (int n = 0; n < 9; n++){
                ulonglong2 e = *reinterpret_cast<const ulonglong2*>(&s_edge[g][n*64 + 4*kq]);
                fma2(q2[n], wq.x, e.x);
                fma2(q2[n], wq.y, e.y);
                fma2(v2[n], wv.x, e.x);
                fma2(v2[n], wv.y, e.y);
            }
        }

        /* attention: per-head (16-lane segment) dot + masked softmax over 9 */
        float a_att[9], vn[9];
        #pragma unroll
        for (int n = 0; n < 9; n++){
            float qn = hsum2(q2[n]) + s_bq[o];
            vn[n]    = hsum2(v2[n]) + s_bv[o];
            float part = keyo * qn;
            part += __shfl_xor_sync(0xffffffffu, part, 8);
            part += __shfl_xor_sync(0xffffffffu, part, 4);
            part += __shfl_xor_sync(0xffffffffu, part, 2);
            part += __shfl_xor_sync(0xffffffffu, part, 1);
            a_att[n] = (s_msk[g][n] == 0) ? -1e10f : part * 0.25f;  /* /sqrt(16) */
        }
        float m = a_att[0];
        #pragma unroll
        for (int n = 1; n < 9; n++) m = fmaxf(m, a_att[n]);
        float ssum = 0.f;
        #pragma unroll
        for (int n = 0; n < 9; n++){ a_att[n] = __expf(a_att[n] - m); ssum += a_att[n]; }
        float inv = 1.f / ssum;
        float ctx = 0.f;
        #pragma unroll
        for (int n = 0; n < 9; n++) ctx += a_att[n] * vn[n];
        ctx *= inv;

        int b = p / SEQL, s = p - b*SEQL;            /* time-major for LSTM */
        g_ctx[((size_t)s*BSZ + b)*ATTD + o] = ctx;
        asm volatile("bar.sync %0, 64;" :: "r"(bar) : "memory");
    }
}

/* ============ kernel 2: xg = ctx @ W_ih^T + (b_ih + b_hh) ================
 * float4-packed weights (16B lane stride, conflict-free): 17 loads per
 * 32 fma2 (was 17/16). grid 888 = 4 col-tiles x 222 owners, single wave. */
__global__ void __launch_bounds__(128) k_xg(
    const float* __restrict__ Wih, const float* __restrict__ bih, const float* __restrict__ bhh)
{
    __shared__ __align__(16) float4 s_w4[16*128];  /* [kq][jj] 4-k packed, 32KB */
    __shared__ float s_b[128];
    __shared__ __align__(16) float s_c[16*64];     /* 16 ctx rows */
    const int tid = threadIdx.x;
    const int jt  = blockIdx.x & 3;
    const int rb  = blockIdx.x >> 2;               /* 0..221 */
    const int j   = jt*128 + tid;

    for (int i = tid; i < 16*128; i += 128){
        int kq = i >> 7, jj = i & 127, jg = jt*128 + jj;
        s_w4[i] = make_float4(Wih[jg*64 + 4*kq],   Wih[jg*64 + 4*kq+1],
                              Wih[jg*64 + 4*kq+2], Wih[jg*64 + 4*kq+3]);
    }
    s_b[tid] = bih[j] + bhh[j];
    __syncthreads();

    for (int r0 = rb*16; r0 < NP; r0 += 222*16){   /* NP % 16 == 0 */
        for (int i = tid; i < 16*64; i += 128) s_c[i] = g_ctx[(size_t)r0*64 + i];
        __syncthreads();
        ull acc2[16];
        #pragma unroll
        for (int r = 0; r < 16; r++) acc2[r] = 0ULL;
        #pragma unroll 4
        for (int kq = 0; kq < 16; kq++){
            ulonglong2 w = *reinterpret_cast<const ulonglong2*>(&s_w4[kq*128 + tid]);
            #pragma unroll
            for (int r = 0; r < 16; r++){
                ulonglong2 c = *reinterpret_cast<const ulonglong2*>(&s_c[r*64 + 4*kq]);
                fma2(acc2[r], w.x, c.x);
                fma2(acc2[r], w.y, c.y);
            }
        }
        float bj = s_b[tid];
        #pragma unroll
        for (int r = 0; r < 16; r++){
            g_xg[(size_t)(r0+r)*G4 + j] = hsum2(acc2[r]) + bj;
        }
        __syncthreads();
    }
}

/* ============ kernel 3: recurrent LSTM scan + output GEMM ================
 * 256 blocks x 256 threads; block owns 8 batch rows. Thread = (cell j,
 * row-half): computes ALL 4 gates for cell j over 4 rows. Per k-quad:
 * 4 coalesced LDG.128 (weights) + 4 broadcast LDS.128 (h) + 32 fma2.
 * Gates reduced in-register (no s_g staging); double-buffered s_h ->
 * ONE __syncthreads per step.                                             */
__global__ void __launch_bounds__(256) k_lstm(
    const float* __restrict__ Wout, const float* __restrict__ bout, float* __restrict__ outp)
{
    __shared__ __align__(16) float s_h[2][8*HIDD]; /* double-buffered, 8 KB */
    __shared__ __align__(16) float s_wo[HIDD*64];  /* W_out^T staging, 32 KB */
    const int tid  = threadIdx.x;
    const int j    = tid & 127;                    /* cell */
    const int half = tid >> 7;                     /* rows 4*half..4*half+3 */
    const int b0   = blockIdx.x * 8;

    for (int i = tid; i < 8*HIDD; i += 256) s_h[0][i] = 0.f;
    float creg[4] = {0.f, 0.f, 0.f, 0.f};
    __syncthreads();

    const ulonglong2* __restrict__ wp = reinterpret_cast<const ulonglong2*>(g_whh4t);
    int p = 0;

    for (int s = 0; s < SEQL; s++){
        ull acc[4][4];                             /* [row][gate] */
        #pragma unroll
        for (int r = 0; r < 4; r++)
            #pragma unroll
            for (int g = 0; g < 4; g++) acc[r][g] = 0ULL;

        #pragma unroll 2
        for (int kq = 0; kq < 32; kq++){
            ulonglong2 w[4];
            #pragma unroll
            for (int g = 0; g < 4; g++) w[g] = __ldg(&wp[kq*G4 + g*128 + j]);
            ulonglong2 h[4];
            #pragma unroll
            for (int r = 0; r < 4; r++)
                h[r] = *reinterpret_cast<const ulonglong2*>(&s_h[p][(half*4 + r)*HIDD + 4*kq]);
            #pragma unroll
            for (int r = 0; r < 4; r++)
                #pragma unroll
                for (int g = 0; g < 4; g++){
                    fma2(acc[r][g], w[g].x, h[r].x);
                    fma2(acc[r][g], w[g].y, h[r].y);
                }
        }

        const float* xgp = g_xg + ((size_t)s*BSZ + b0)*G4;
        #pragma unroll
        for (int r = 0; r < 4; r++){
            int row = half*4 + r;
            const float* x = xgp + (size_t)row*G4;
            float gi = hsum2(acc[r][0]) + __ldg(&x[j]);
            float gf = hsum2(acc[r][1]) + __ldg(&x[128 + j]);
            float gg = hsum2(acc[r][2]) + __ldg(&x[256 + j]);
            float go = hsum2(acc[r][3]) + __ldg(&x[384 + j]);
            float ig = sigm(gi), fg = sigm(gf), gt = tanhfast(gg), og = sigm(go);
            float c  = fg*creg[r] + ig*gt;
            creg[r]  = c;
            s_h[1-p][row*HIDD + j] = og * tanhfast(c);
        }
        p ^= 1;
        __syncthreads();
    }

    /* out = h_last @ W_out^T + b_out ; stage W_out^T [jj][oo] in smem */
    for (int i = tid; i < 64*HIDD; i += 256){
        int oo = i & 63, jj = i >> 6;
        s_wo[jj*64 + oo] = Wout[oo*HIDD + jj];
    }
    __syncthreads();
    #pragma unroll
    for (int q = 0; q < 2; q++){                   /* 512 outputs / 256 thr */
        int idx = q*256 + tid;
        int r = idx >> 6, oo = idx & 63;
        float acc = __ldg(&bout[oo]);
        #pragma unroll 8
        for (int jj = 0; jj < HIDD; jj++) acc += s_wo[jj*64 + oo] * s_h[p][r*HIDD + jj];
        outp[(size_t)(b0 + r)*64 + oo] = acc;
    }
}

/* ======================================================================== */
extern "C" void kernel_launch(void* const* d_in, const int* in_sizes, int n_in,
                              void* d_out, int out_size)
{
    const float* seqs = (const float*)d_in[0];
    const float* ets  = (const float*)d_in[1];
    const int*   msk  = (const int*)  d_in[2];
    const float* Wfus = (const float*)d_in[3];
    const float* bfus = (const float*)d_in[4];
    const float* Wk   = (const float*)d_in[5];
    const float* bk   = (const float*)d_in[6];
    const float* Wq   = (const float*)d_in[7];
    const float* bq   = (const float*)d_in[8];
    const float* Wv   = (const float*)d_in[9];
    const float* bv   = (const float*)d_in[10];
    const float* Wih  = (const float*)d_in[11];
    const float* Whh  = (const float*)d_in[12];
    const float* bih  = (const float*)d_in[13];
    const float* bhh  = (const float*)d_in[14];
    const float* Wout = (const float*)d_in[15];
    const float* bout = (const float*)d_in[16];
    float* outp = (float*)d_out;

    k_pack<<<32, 512>>>(Whh);
    k_ctx <<<740, 128>>>(seqs, ets, msk, Wfus, bfus, Wk, bk, Wq, bq, Wv, bv);
    k_xg  <<<888, 128>>>(Wih, bih, bhh);
    k_lstm<<<256, 256>>>(Wout, bout, outp);
}

// round 6
// speedup vs baseline: 1.0178x; 1.0178x over previous
#include <cuda_runtime.h>

#define BSZ  2048
#define SEQL 50
#define NP   (BSZ*SEQL)      /* 102400 pairs */
#define ATTD 64
#define HIDD 128
#define G4   512             /* 4*HID gates */
#define FIN  19              /* 6 + 4 + 9 fused input dim */

typedef unsigned long long ull;

/* ---------------- device scratch (no cudaMalloc allowed) ---------------- */
__device__ float  g_ctx[(size_t)NP * ATTD];        /* [s][b][64]  26 MB  */
__device__ float  g_xg [(size_t)NP * G4];          /* [s][b][512] 210 MB */
__device__ float4 g_whh4t[(HIDD/4) * G4];          /* [kq][col] packed W_hh^T */

/* ---------------- f32x2 helpers (2 MACs / instr on sm_103a) ------------- */
__device__ __forceinline__ void fma2(ull& d, ull a, ull b){
    asm("fma.rn.f32x2 %0, %1, %2, %0;" : "+l"(d) : "l"(a), "l"(b));
}
__device__ __forceinline__ float2 unpk(ull v){
    float2 r; asm("mov.b64 {%0, %1}, %2;" : "=f"(r.x), "=f"(r.y) : "l"(v)); return r;
}
__device__ __forceinline__ float hsum2(ull v){ float2 f = unpk(v); return f.x + f.y; }
__device__ __forceinline__ float sigm(float x){ return 1.f/(1.f + __expf(-x)); }
__device__ __forceinline__ float tanhfast(float x){ return 1.f - 2.f/(__expf(2.f*x) + 1.f); }

/* ============ kernel 0: transpose+pack W_hh -> [kq][col] float4 ========= */
__global__ void k_pack(const float* __restrict__ Whh){
    int t = threadIdx.x, kq = blockIdx.x;             /* <<<32,512>>> */
    g_whh4t[kq*G4 + t] = make_float4(Whh[t*HIDD + 4*kq],   Whh[t*HIDD + 4*kq+1],
                                     Whh[t*HIDD + 4*kq+2], Whh[t*HIDD + 4*kq+3]);
}

/* ============ kernel 1: fused edge-MLP + 4-head attention -> ctx ======== */
__global__ void __launch_bounds__(128) k_ctx(
    const float* __restrict__ seqs, const float* __restrict__ ets, const int* __restrict__ masks,
    const float* __restrict__ Wfus, const float* __restrict__ bfus,
    const float* __restrict__ Wk,   const float* __restrict__ bk,
    const float* __restrict__ Wq,   const float* __restrict__ bq,
    const float* __restrict__ Wv,   const float* __restrict__ bv)
{
    __shared__ __align__(16) float  s_fus[FIN*64];     /* [k][o] */
    __shared__ __align__(16) float4 s_wq4[16*64];      /* [kq][o] 4-k packed */
    __shared__ __align__(16) float4 s_wv4[16*64];
    __shared__ __align__(16) float  s_wk[6*64];
    __shared__ float s_bq[64], s_bv[64], s_bfus[64], s_bk[64];
    __shared__ __align__(16) float  s_edge[2][9*64];
    __shared__ __align__(16) float  s_raw[2][90];
    __shared__ int s_msk[2][9];

    const int tid = threadIdx.x;
    for (int i = tid; i < FIN*64; i += 128){ int k=i>>6, o=i&63; s_fus[i] = Wfus[o*FIN + k]; }
    for (int i = tid; i < 16*64; i += 128){
        int kq=i>>6, o=i&63;
        s_wq4[i] = make_float4(Wq[o*64+4*kq], Wq[o*64+4*kq+1], Wq[o*64+4*kq+2], Wq[o*64+4*kq+3]);
        s_wv4[i] = make_float4(Wv[o*64+4*kq], Wv[o*64+4*kq+1], Wv[o*64+4*kq+2], Wv[o*64+4*kq+3]);
    }
    for (int i = tid; i < 6*64; i += 128){ int k=i>>6, o=i&63; s_wk[i] = Wk[o*6 + k]; }
    if (tid < 64){ s_bq[tid]=bq[tid]; s_bv[tid]=bv[tid]; s_bfus[tid]=bfus[tid]; s_bk[tid]=bk[tid]; }
    __syncthreads();

    const int g   = tid >> 6;
    const int o   = tid & 63;
    const int bar = g + 1;                 /* named barrier id, 64 threads */
    const int ggid    = blockIdx.x*2 + g;
    const int ngroups = gridDim.x*2;

    for (int p = ggid; p < NP; p += ngroups){
        const float* sq = seqs + (size_t)p*54;
        const float* se = ets  + (size_t)p*36;
        for (int i = o; i < 90; i += 64) s_raw[g][i] = (i < 54) ? sq[i] : se[i-54];
        if (o < 9) s_msk[g][o] = masks[(size_t)p*9 + o];
        asm volatile("bar.sync %0, 64;" :: "r"(bar) : "memory");

        /* edge_info[n][o] = [seq(6),etype(4),onehot9] @ Wfus^T + bfus */
        float keyo;
        #pragma unroll
        for (int n = 0; n < 9; n++){
            float acc = s_bfus[o] + s_fus[(10+n)*64 + o];     /* one-hot loc */
            #pragma unroll
            for (int k = 0; k < 6; k++) acc += s_fus[k*64+o]     * s_raw[g][n*6+k];
            #pragma unroll
            for (int k = 0; k < 4; k++) acc += s_fus[(6+k)*64+o] * s_raw[g][54 + n*4 + k];
            s_edge[g][n*64 + o] = acc;
        }
        {   /* key from self (center cell n=4) */
            float acck = s_bk[o];
            #pragma unroll
            for (int k = 0; k < 6; k++) acck += s_wk[k*64+o] * s_raw[g][24 + k];
            keyo = acck;
        }
        asm volatile("bar.sync %0, 64;" :: "r"(bar) : "memory");

        /* Q,V: 9 slots x 64 cols, 4-k quads */
        ull q2[9], v2[9];
        #pragma unroll
        for (int n = 0; n < 9; n++){ q2[n] = 0ULL; v2[n] = 0ULL; }
        #pragma unroll 4
        for (int kq = 0; kq < 16; kq++){
            ulonglong2 wq = *reinterpret_cast<const ulonglong2*>(&s_wq4[kq*64 + o]);
            ulonglong2 wv = *reinterpret_cast<const ulonglong2*>(&s_wv4[kq*64 + o]);
            #pragma unroll
            for (int n = 0; n < 9; n++){
                ulonglong2 e = *reinterpret_cast<const ulonglong2*>(&s_edge[g][n*64 + 4*kq]);
                fma2(q2[n], wq.x, e.x);
                fma2(q2[n], wq.y, e.y);
                fma2(v2[n], wv.x, e.x);
                fma2(v2[n], wv.y, e.y);
            }
        }

        /* attention: per-head (16-lane segment) dot + masked softmax over 9 */
        float a_att[9], vn[9];
        #pragma unroll
        for (int n = 0; n < 9; n++){
            float qn = hsum2(q2[n]) + s_bq[o];
            vn[n]    = hsum2(v2[n]) + s_bv[o];
            float part = keyo * qn;
            part += __shfl_xor_sync(0xffffffffu, part, 8);
            part += __shfl_xor_sync(0xffffffffu, part, 4);
            part += __shfl_xor_sync(0xffffffffu, part, 2);
            part += __shfl_xor_sync(0xffffffffu, part, 1);
            a_att[n] = (s_msk[g][n] == 0) ? -1e10f : part * 0.25f;  /* /sqrt(16) */
        }
        float m = a_att[0];
        #pragma unroll
        for (int n = 1; n < 9; n++) m = fmaxf(m, a_att[n]);
        float ssum = 0.f;
        #pragma unroll
        for (int n = 0; n < 9; n++){ a_att[n] = __expf(a_att[n] - m); ssum += a_att[n]; }
        float inv = 1.f / ssum;
        float ctx = 0.f;
        #pragma unroll
        for (int n = 0; n < 9; n++) ctx += a_att[n] * vn[n];
        ctx *= inv;

        int b = p / SEQL, s = p - b*SEQL;            /* time-major for LSTM */
        g_ctx[((size_t)s*BSZ + b)*ATTD + o] = ctx;
        asm volatile("bar.sync %0, 64;" :: "r"(bar) : "memory");
    }
}

/* ============ kernel 2: xg = ctx @ W_ih^T + (b_ih + b_hh) =============== */
__global__ void __launch_bounds__(128) k_xg(
    const float* __restrict__ Wih, const float* __restrict__ bih, const float* __restrict__ bhh)
{
    __shared__ __align__(16) float4 s_w4[16*128];  /* [kq][jj] 4-k packed, 32KB */
    __shared__ float s_b[128];
    __shared__ __align__(16) float s_c[16*64];     /* 16 ctx rows */
    const int tid = threadIdx.x;
    const int jt  = blockIdx.x & 3;
    const int rb  = blockIdx.x >> 2;               /* 0..221 */
    const int j   = jt*128 + tid;

    for (int i = tid; i < 16*128; i += 128){
        int kq = i >> 7, jj = i & 127, jg = jt*128 + jj;
        s_w4[i] = make_float4(Wih[jg*64 + 4*kq],   Wih[jg*64 + 4*kq+1],
                              Wih[jg*64 + 4*kq+2], Wih[jg*64 + 4*kq+3]);
    }
    s_b[tid] = bih[j] + bhh[j];
    __syncthreads();

    for (int r0 = rb*16; r0 < NP; r0 += 222*16){   /* NP % 16 == 0 */
        for (int i = tid; i < 16*64; i += 128) s_c[i] = g_ctx[(size_t)r0*64 + i];
        __syncthreads();
        ull acc2[16];
        #pragma unroll
        for (int r = 0; r < 16; r++) acc2[r] = 0ULL;
        #pragma unroll 4
        for (int kq = 0; kq < 16; kq++){
            ulonglong2 w = *reinterpret_cast<const ulonglong2*>(&s_w4[kq*128 + tid]);
            #pragma unroll
            for (int r = 0; r < 16; r++){
                ulonglong2 c = *reinterpret_cast<const ulonglong2*>(&s_c[r*64 + 4*kq]);
                fma2(acc2[r], w.x, c.x);
                fma2(acc2[r], w.y, c.y);
            }
        }
        float bj = s_b[tid];
        #pragma unroll
        for (int r = 0; r < 16; r++){
            g_xg[(size_t)(r0+r)*G4 + j] = hsum2(acc2[r]) + bj;
        }
        __syncthreads();
    }
}

/* ============ kernel 3: recurrent LSTM scan + output GEMM ================
 * 256 blocks x 512 threads (2 blocks/SM forced), block owns 8 batch rows.
 * Thread = gate column t. Per kq: 1 coalesced LDG.128 (4 k's of own col,
 * no duplication) + 8 broadcast LDS.128 (h) + 16 fma2.                    */
__global__ void __launch_bounds__(512, 2) k_lstm(
    const float* __restrict__ Wout, const float* __restrict__ bout, float* __restrict__ outp)
{
    __shared__ __align__(16) float s_h[8*HIDD];    /* 4 KB  */
    __shared__ __align__(16) float s_g[64*HIDD];   /* 32 KB: gates 8*G4=4096,
                                                      epilogue W_out^T 8192 */
    const int tid = threadIdx.x;
    const int b0  = blockIdx.x * 8;
    for (int i = tid; i < 8*HIDD; i += 512) s_h[i] = 0.f;
    float creg[2] = {0.f, 0.f};
    __syncthreads();

    const ulonglong2* __restrict__ wp = reinterpret_cast<const ulonglong2*>(g_whh4t);

    for (int s = 0; s < SEQL; s++){
        ull acc2[8];
        #pragma unroll
        for (int r = 0; r < 8; r++) acc2[r] = 0ULL;
        #pragma unroll 8
        for (int kq = 0; kq < 32; kq++){
            ulonglong2 w = __ldg(&wp[kq*G4 + tid]);         /* LDG.128 coalesced */
            #pragma unroll
            for (int r = 0; r < 8; r++){
                ulonglong2 h = *reinterpret_cast<const ulonglong2*>(&s_h[r*HIDD + 4*kq]);
                fma2(acc2[r], w.x, h.x);
                fma2(acc2[r], w.y, h.y);
            }
        }
        const float* xgp = g_xg + ((size_t)s*BSZ + b0)*G4;
        #pragma unroll
        for (int r = 0; r < 8; r++){
            s_g[r*G4 + tid] = hsum2(acc2[r]) + __ldg(&xgp[r*G4 + tid]);
        }
        __syncthreads();
        #pragma unroll
        for (int q = 0; q < 2; q++){                        /* 1024 cells / 512 thr */
            int cell = q*512 + tid;
            int r = cell >> 7, j = cell & 127;
            float ig = sigm(s_g[r*G4 + j]);
            float fg = sigm(s_g[r*G4 + 128 + j]);
            float gg = tanhfast(s_g[r*G4 + 256 + j]);
            float og = sigm(s_g[r*G4 + 384 + j]);
            float c  = fg*creg[q] + ig*gg;
            creg[q]  = c;
            s_h[r*HIDD + j] = og * tanhfast(c);
        }
        __syncthreads();
    }

    /* out = h_last @ W_out^T + b_out ; stage W_out^T [jj][oo] in s_g */
    float* s_wo = s_g;
    for (int i = tid; i < 64*HIDD; i += 512){
        int oo = i & 63, jj = i >> 6;
        s_wo[jj*64 + oo] = Wout[oo*HIDD + jj];
    }
    __syncthreads();
    {
        int r = tid >> 6, oo = tid & 63;                    /* 8 rows x 64 cols */
        float acc = __ldg(&bout[oo]);
        #pragma unroll 8
        for (int jj = 0; jj < HIDD; jj++) acc += s_wo[jj*64 + oo] * s_h[r*HIDD + jj];
        outp[(size_t)(b0 + r)*64 + oo] = acc;
    }
}

/* ======================================================================== */
extern "C" void kernel_launch(void* const* d_in, const int* in_sizes, int n_in,
                              void* d_out, int out_size)
{
    const float* seqs = (const float*)d_in[0];
    const float* ets  = (const float*)d_in[1];
    const int*   msk  = (const int*)  d_in[2];
    const float* Wfus = (const float*)d_in[3];
    const float* bfus = (const float*)d_in[4];
    const float* Wk   = (const float*)d_in[5];
    const float* bk   = (const float*)d_in[6];
    const float* Wq   = (const float*)d_in[7];
    const float* bq   = (const float*)d_in[8];
    const float* Wv   = (const float*)d_in[9];
    const float* bv   = (const float*)d_in[10];
    const float* Wih  = (const float*)d_in[11];
    const float* Whh  = (const float*)d_in[12];
    const float* bih  = (const float*)d_in[13];
    const float* bhh  = (const float*)d_in[14];
    const float* Wout = (const float*)d_in[15];
    const float* bout = (const float*)d_in[16];
    float* outp = (float*)d_out;

    k_pack<<<32, 512>>>(Whh);
    k_ctx <<<740, 128>>>(seqs, ets, msk, Wfus, bfus, Wk, bk, Wq, bq, Wv, bv);
    k_xg  <<<888, 128>>>(Wih, bih, bhh);
    k_lstm<<<256, 512>>>(Wout, bout, outp);
}

// round 7
// speedup vs baseline: 1.0823x; 1.0633x over previous
#include <cuda_runtime.h>

#define BSZ  2048
#define SEQL 50
#define NP   (BSZ*SEQL)      /* 102400 pairs */
#define ATTD 64
#define HIDD 128
#define G4   512             /* 4*HID gates */
#define FIN  19              /* 6 + 4 + 9 fused input dim */

typedef unsigned long long ull;

/* ---------------- device scratch (no cudaMalloc allowed) ---------------- */
__device__ float  g_ctx[(size_t)NP * ATTD];        /* [s][b][64]  26 MB  */
__device__ float  g_xg [(size_t)NP * G4];          /* [s][b][512] 210 MB */
__device__ float4 g_whh4t[(HIDD/4) * G4];          /* [kq][col] packed W_hh^T */

/* ---------------- f32x2 helpers (2 MACs / instr on sm_103a) ------------- */
__device__ __forceinline__ void fma2(ull& d, ull a, ull b){
    asm("fma.rn.f32x2 %0, %1, %2, %0;" : "+l"(d) : "l"(a), "l"(b));
}
__device__ __forceinline__ float2 unpk(ull v){
    float2 r; asm("mov.b64 {%0, %1}, %2;" : "=f"(r.x), "=f"(r.y) : "l"(v)); return r;
}
__device__ __forceinline__ float hsum2(ull v){ float2 f = unpk(v); return f.x + f.y; }
__device__ __forceinline__ float sigm(float x){ return 1.f/(1.f + __expf(-x)); }
__device__ __forceinline__ float tanhfast(float x){ return 1.f - 2.f/(__expf(2.f*x) + 1.f); }

/* ============ kernel 0: transpose+pack W_hh -> [kq][col] float4 ========= */
__global__ void k_pack(const float* __restrict__ Whh){
    int t = threadIdx.x, kq = blockIdx.x;             /* <<<32,512>>> */
    g_whh4t[kq*G4 + t] = make_float4(Whh[t*HIDD + 4*kq],   Whh[t*HIDD + 4*kq+1],
                                     Whh[t*HIDD + 4*kq+2], Whh[t*HIDD + 4*kq+3]);
}

/* ============ kernel 1: fused edge-MLP + 4-head attention -> ctx ======== */
__global__ void __launch_bounds__(128) k_ctx(
    const float* __restrict__ seqs, const float* __restrict__ ets, const int* __restrict__ masks,
    const float* __restrict__ Wfus, const float* __restrict__ bfus,
    const float* __restrict__ Wk,   const float* __restrict__ bk,
    const float* __restrict__ Wq,   const float* __restrict__ bq,
    const float* __restrict__ Wv,   const float* __restrict__ bv)
{
    __shared__ __align__(16) float  s_fus[FIN*64];     /* [k][o] */
    __shared__ __align__(16) float4 s_wq4[16*64];      /* [kq][o] 4-k packed */
    __shared__ __align__(16) float4 s_wv4[16*64];
    __shared__ __align__(16) float  s_wk[6*64];
    __shared__ float s_bq[64], s_bv[64], s_bfus[64], s_bk[64];
    __shared__ __align__(16) float  s_edge[2][9*64];
    __shared__ __align__(16) float  s_raw[2][90];
    __shared__ int s_msk[2][9];

    const int tid = threadIdx.x;
    for (int i = tid; i < FIN*64; i += 128){ int k=i>>6, o=i&63; s_fus[i] = Wfus[o*FIN + k]; }
    for (int i = tid; i < 16*64; i += 128){
        int kq=i>>6, o=i&63;
        s_wq4[i] = make_float4(Wq[o*64+4*kq], Wq[o*64+4*kq+1], Wq[o*64+4*kq+2], Wq[o*64+4*kq+3]);
        s_wv4[i] = make_float4(Wv[o*64+4*kq], Wv[o*64+4*kq+1], Wv[o*64+4*kq+2], Wv[o*64+4*kq+3]);
    }
    for (int i = tid; i < 6*64; i += 128){ int k=i>>6, o=i&63; s_wk[i] = Wk[o*6 + k]; }
    if (tid < 64){ s_bq[tid]=bq[tid]; s_bv[tid]=bv[tid]; s_bfus[tid]=bfus[tid]; s_bk[tid]=bk[tid]; }
    __syncthreads();

    const int g   = tid >> 6;
    const int o   = tid & 63;
    const int bar = g + 1;                 /* named barrier id, 64 threads */
    const int ggid    = blockIdx.x*2 + g;
    const int ngroups = gridDim.x*2;

    for (int p = ggid; p < NP; p += ngroups){
        const float* sq = seqs + (size_t)p*54;
        const float* se = ets  + (size_t)p*36;
        for (int i = o; i < 90; i += 64) s_raw[g][i] = (i < 54) ? sq[i] : se[i-54];
        if (o < 9) s_msk[g][o] = masks[(size_t)p*9 + o];
        asm volatile("bar.sync %0, 64;" :: "r"(bar) : "memory");

        /* edge_info[n][o] = [seq(6),etype(4),onehot9] @ Wfus^T + bfus */
        float keyo;
        #pragma unroll
        for (int n = 0; n < 9; n++){
            float acc = s_bfus[o] + s_fus[(10+n)*64 + o];     /* one-hot loc */
            #pragma unroll
            for (int k = 0; k < 6; k++) acc += s_fus[k*64+o]     * s_raw[g][n*6+k];
            #pragma unroll
            for (int k = 0; k < 4; k++) acc += s_fus[(6+k)*64+o] * s_raw[g][54 + n*4 + k];
            s_edge[g][n*64 + o] = acc;
        }
        {   /* key from self (center cell n=4) */
            float acck = s_bk[o];
            #pragma unroll
            for (int k = 0; k < 6; k++) acck += s_wk[k*64+o] * s_raw[g][24 + k];
            keyo = acck;
        }
        asm volatile("bar.sync %0, 64;" :: "r"(bar) : "memory");

        /* Q,V: 9 slots x 64 cols, 4-k quads */
        ull q2[9], v2[9];
        #pragma unroll
        for (int n = 0; n < 9; n++){ q2[n] = 0ULL; v2[n] = 0ULL; }
        #pragma unroll 4
        for (int kq = 0; kq < 16; kq++){
            ulonglong2 wq = *reinterpret_cast<const ulonglong2*>(&s_wq4[kq*64 + o]);
            ulonglong2 wv = *reinterpret_cast<const ulonglong2*>(&s_wv4[kq*64 + o]);
            #pragma unroll
            for (int n = 0; n < 9; n++){
                ulonglong2 e = *reinterpret_cast<const ulonglong2*>(&s_edge[g][n*64 + 4*kq]);
                fma2(q2[n], wq.x, e.x);
                fma2(q2[n], wq.y, e.y);
                fma2(v2[n], wv.x, e.x);
                fma2(v2[n], wv.y, e.y);
            }
        }

        /* attention: per-head (16-lane segment) dot + masked softmax over 9 */
        float a_att[9], vn[9];
        #pragma unroll
        for (int n = 0; n < 9; n++){
            float qn = hsum2(q2[n]) + s_bq[o];
            vn[n]    = hsum2(v2[n]) + s_bv[o];
            float part = keyo * qn;
            part += __shfl_xor_sync(0xffffffffu, part, 8);
            part += __shfl_xor_sync(0xffffffffu, part, 4);
            part += __shfl_xor_sync(0xffffffffu, part, 2);
            part += __shfl_xor_sync(0xffffffffu, part, 1);
            a_att[n] = (s_msk[g][n] == 0) ? -1e10f : part * 0.25f;  /* /sqrt(16) */
        }
        float m = a_att[0];
        #pragma unroll
        for (int n = 1; n < 9; n++) m = fmaxf(m, a_att[n]);
        float ssum = 0.f;
        #pragma unroll
        for (int n = 0; n < 9; n++){ a_att[n] = __expf(a_att[n] - m); ssum += a_att[n]; }
        float inv = 1.f / ssum;
        float ctx = 0.f;
        #pragma unroll
        for (int n = 0; n < 9; n++) ctx += a_att[n] * vn[n];
        ctx *= inv;

        int b = p / SEQL, s = p - b*SEQL;            /* time-major for LSTM */
        g_ctx[((size_t)s*BSZ + b)*ATTD + o] = ctx;
        asm volatile("bar.sync %0, 64;" :: "r"(bar) : "memory");
    }
}

/* ============ kernel 2: xg = ctx @ W_ih^T + (b_ih + b_hh) =============== */
__global__ void __launch_bounds__(128) k_xg(
    const float* __restrict__ Wih, const float* __restrict__ bih, const float* __restrict__ bhh)
{
    __shared__ __align__(16) float4 s_w4[16*128];  /* [kq][jj] 4-k packed, 32KB */
    __shared__ float s_b[128];
    __shared__ __align__(16) float s_c[16*64];     /* 16 ctx rows */
    const int tid = threadIdx.x;
    const int jt  = blockIdx.x & 3;
    const int rb  = blockIdx.x >> 2;               /* 0..221 */
    const int j   = jt*128 + tid;

    for (int i = tid; i < 16*128; i += 128){
        int kq = i >> 7, jj = i & 127, jg = jt*128 + jj;
        s_w4[i] = make_float4(Wih[jg*64 + 4*kq],   Wih[jg*64 + 4*kq+1],
                              Wih[jg*64 + 4*kq+2], Wih[jg*64 + 4*kq+3]);
    }
    s_b[tid] = bih[j] + bhh[j];
    __syncthreads();

    for (int r0 = rb*16; r0 < NP; r0 += 222*16){   /* NP % 16 == 0 */
        for (int i = tid; i < 16*64; i += 128) s_c[i] = g_ctx[(size_t)r0*64 + i];
        __syncthreads();
        ull acc2[16];
        #pragma unroll
        for (int r = 0; r < 16; r++) acc2[r] = 0ULL;
        #pragma unroll 4
        for (int kq = 0; kq < 16; kq++){
            ulonglong2 w = *reinterpret_cast<const ulonglong2*>(&s_w4[kq*128 + tid]);
            #pragma unroll
            for (int r = 0; r < 16; r++){
                ulonglong2 c = *reinterpret_cast<const ulonglong2*>(&s_c[r*64 + 4*kq]);
                fma2(acc2[r], w.x, c.x);
                fma2(acc2[r], w.y, c.y);
            }
        }
        float bj = s_b[tid];
        #pragma unroll
        for (int r = 0; r < 16; r++){
            g_xg[(size_t)(r0+r)*G4 + j] = hsum2(acc2[r]) + bj;
        }
        __syncthreads();
    }
}

/* ============ kernel 3: recurrent LSTM scan + output GEMM ================
 * 256 blocks x 512 threads (2/SM), block owns 8 batch rows.
 * Thread tile = 4 rows x 2 gate-cols {c, c+256}: per kq 2 coalesced
 * LDG.128 + 4 broadcast LDS.128 + 16 fma2 (LDS halved vs 1-col layout).
 * xg bias loads prefetched to top of step to hide L2 latency.             */
__global__ void __launch_bounds__(512, 2) k_lstm(
    const float* __restrict__ Wout, const float* __restrict__ bout, float* __restrict__ outp)
{
    __shared__ __align__(16) float s_h[8*HIDD];    /* 4 KB  */
    __shared__ __align__(16) float s_g[64*HIDD];   /* 32 KB: gates 8*G4=4096,
                                                      epilogue W_out^T 8192 */
    const int tid = threadIdx.x;
    const int c   = tid & 255;                     /* owns cols c and c+256 */
    const int rh  = tid >> 8;                      /* rows 4rh..4rh+3 */
    const int b0  = blockIdx.x * 8;
    for (int i = tid; i < 8*HIDD; i += 512) s_h[i] = 0.f;
    float creg[2] = {0.f, 0.f};
    __syncthreads();

    const ulonglong2* __restrict__ wp = reinterpret_cast<const ulonglong2*>(g_whh4t);

    for (int s = 0; s < SEQL; s++){
        /* prefetch xg gate biases for own 8 outputs (hide L2 latency) */
        const float* xgp = g_xg + ((size_t)s*BSZ + b0)*G4;
        float xv0[4], xv1[4];
        #pragma unroll
        for (int r = 0; r < 4; r++){
            int row = rh*4 + r;
            xv0[r] = __ldg(&xgp[(size_t)row*G4 + c]);
            xv1[r] = __ldg(&xgp[(size_t)row*G4 + c + 256]);
        }

        ull acc0[4], acc1[4];
        #pragma unroll
        for (int r = 0; r < 4; r++){ acc0[r] = 0ULL; acc1[r] = 0ULL; }

        #pragma unroll 4
        for (int kq = 0; kq < 32; kq++){
            ulonglong2 w0 = __ldg(&wp[kq*G4 + c]);          /* LDG.128 coalesced */
            ulonglong2 w1 = __ldg(&wp[kq*G4 + 256 + c]);
            ulonglong2 h[4];
            #pragma unroll
            for (int r = 0; r < 4; r++)
                h[r] = *reinterpret_cast<const ulonglong2*>(&s_h[(rh*4 + r)*HIDD + 4*kq]);
            #pragma unroll
            for (int r = 0; r < 4; r++){
                fma2(acc0[r], w0.x, h[r].x);
                fma2(acc0[r], w0.y, h[r].y);
                fma2(acc1[r], w1.x, h[r].x);
                fma2(acc1[r], w1.y, h[r].y);
            }
        }

        #pragma unroll
        for (int r = 0; r < 4; r++){
            int row = rh*4 + r;
            s_g[row*G4 + c]       = hsum2(acc0[r]) + xv0[r];
            s_g[row*G4 + c + 256] = hsum2(acc1[r]) + xv1[r];
        }
        __syncthreads();
        #pragma unroll
        for (int q = 0; q < 2; q++){                        /* 1024 cells / 512 thr */
            int cell = q*512 + tid;
            int r = cell >> 7, j = cell & 127;
            float ig = sigm(s_g[r*G4 + j]);
            float fg = sigm(s_g[r*G4 + 128 + j]);
            float gg = tanhfast(s_g[r*G4 + 256 + j]);
            float og = sigm(s_g[r*G4 + 384 + j]);
            float cc = fg*creg[q] + ig*gg;
            creg[q]  = cc;
            s_h[r*HIDD + j] = og * tanhfast(cc);
        }
        __syncthreads();
    }

    /* out = h_last @ W_out^T + b_out ; stage W_out^T [jj][oo] in s_g */
    float* s_wo = s_g;
    for (int i = tid; i < 64*HIDD; i += 512){
        int oo = i & 63, jj = i >> 6;
        s_wo[jj*64 + oo] = Wout[oo*HIDD + jj];
    }
    __syncthreads();
    {
        int r = tid >> 6, oo = tid & 63;                    /* 8 rows x 64 cols */
        float acc = __ldg(&bout[oo]);
        #pragma unroll 8
        for (int jj = 0; jj < HIDD; jj++) acc += s_wo[jj*64 + oo] * s_h[r*HIDD + jj];
        outp[(size_t)(b0 + r)*64 + oo] = acc;
    }
}

/* ======================================================================== */
extern "C" void kernel_launch(void* const* d_in, const int* in_sizes, int n_in,
                              void* d_out, int out_size)
{
    const float* seqs = (const float*)d_in[0];
    const float* ets  = (const float*)d_in[1];
    const int*   msk  = (const int*)  d_in[2];
    const float* Wfus = (const float*)d_in[3];
    const float* bfus = (const float*)d_in[4];
    const float* Wk   = (const float*)d_in[5];
    const float* bk   = (const float*)d_in[6];
    const float* Wq   = (const float*)d_in[7];
    const float* bq   = (const float*)d_in[8];
    const float* Wv   = (const float*)d_in[9];
    const float* bv   = (const float*)d_in[10];
    const float* Wih  = (const float*)d_in[11];
    const float* Whh  = (const float*)d_in[12];
    const float* bih  = (const float*)d_in[13];
    const float* bhh  = (const float*)d_in[14];
    const float* Wout = (const float*)d_in[15];
    const float* bout = (const float*)d_in[16];
    float* outp = (float*)d_out;

    k_pack<<<32, 512>>>(Whh);
    k_ctx <<<740, 128>>>(seqs, ets, msk, Wfus, bfus, Wk, bk, Wq, bq, Wv, bv);
    k_xg  <<<888, 128>>>(Wih, bih, bhh);
    k_lstm<<<256, 512>>>(Wout, bout, outp);
}

// round 8
// speedup vs baseline: 1.2071x; 1.1153x over previous
#include <cuda_runtime.h>

#define BSZ  2048
#define SEQL 50
#define NP   (BSZ*SEQL)      /* 102400 pairs */
#define ATTD 64
#define HIDD 128
#define G4   512             /* 4*HID gates */

typedef unsigned long long ull;

/* ---------------- device scratch (no cudaMalloc allowed) ---------------- */
__device__ float  g_ctx[(size_t)NP * ATTD];        /* [s][b][64]  26 MB  */
__device__ float  g_xg [(size_t)NP * G4];          /* [s][b][512] 210 MB */
__device__ float4 g_whh4t[(HIDD/4) * G4];          /* [kq][col] packed W_hh^T */

/* ---------------- f32x2 helpers (2 MACs / instr on sm_103a) ------------- */
__device__ __forceinline__ void fma2(ull& d, ull a, ull b){
    asm("fma.rn.f32x2 %0, %1, %2, %0;" : "+l"(d) : "l"(a), "l"(b));
}
__device__ __forceinline__ float2 unpk(ull v){
    float2 r; asm("mov.b64 {%0, %1}, %2;" : "=f"(r.x), "=f"(r.y) : "l"(v)); return r;
}
__device__ __forceinline__ float hsum2(ull v){ float2 f = unpk(v); return f.x + f.y; }
__device__ __forceinline__ ull pack2(float x){
    ull r; asm("mov.b64 %0, {%1, %1};" : "=l"(r) : "f"(x)); return r;
}
__device__ __forceinline__ float sigm(float x){ return 1.f/(1.f + __expf(-x)); }
__device__ __forceinline__ float tanhfast(float x){ return 1.f - 2.f/(__expf(2.f*x) + 1.f); }

/* ============ kernel 0: transpose+pack W_hh -> [kq][col] float4 ========= */
__global__ void k_pack(const float* __restrict__ Whh){
    int t = threadIdx.x, kq = blockIdx.x;             /* <<<32,512>>> */
    g_whh4t[kq*G4 + t] = make_float4(Whh[t*HIDD + 4*kq],   Whh[t*HIDD + 4*kq+1],
                                     Whh[t*HIDD + 4*kq+2], Whh[t*HIDD + 4*kq+3]);
}

/* ============ kernel 1: edge attention via algebraic folding ============
 * att[n,h] = x_n . wtil_h + gamma_h + beta_h   (Q-GEMM folded through key)
 * ctx[h]   = Wv_h (Wfus xbar_h + bfus) + bv    (V-GEMM folded through att)
 * 64 threads/pair = 4 heads x 16 lanes; per-head reductions stay inside a
 * 16-lane quarter-warp (shfl). u / ebar staged per-head in smem.          */
__global__ void __launch_bounds__(128) k_ctx(
    const float* __restrict__ seqs, const float* __restrict__ ets, const int* __restrict__ masks,
    const float* __restrict__ Wfus, const float* __restrict__ bfus,
    const float* __restrict__ Wk,   const float* __restrict__ bk,
    const float* __restrict__ Wq,   const float* __restrict__ bq,
    const float* __restrict__ Wv,   const float* __restrict__ bv)
{
    __shared__ __align__(16) float  s_fus[20*64];   /* [k][o]; row19 = bfus */
    __shared__ __align__(16) float2 s_fT[32*20];    /* [pair][k] Wfus rows  */
    __shared__ __align__(16) float2 s_wq2[64*32];   /* [o][pair]            */
    __shared__ __align__(16) float2 s_wv2[32*64];   /* [pair][o]            */
    __shared__ __align__(16) float  s_wk[6*64];     /* [k][o]               */
    __shared__ float s_bq[64], s_bv[64], s_bk[64];
    __shared__ __align__(16) float  s_raw[2][96];
    __shared__ __align__(16) float2 s_u[2][4*32];   /* [g][h*32+pair]       */
    __shared__ __align__(16) float2 s_e[2][4*32];
    __shared__ int s_msk[2][12];

    const int tid = threadIdx.x;
    for (int i = tid; i < 20*64; i += 128){
        int k = i >> 6, o = i & 63;
        s_fus[i] = (k < 19) ? Wfus[o*19 + k] : bfus[o];
    }
    for (int i = tid; i < 32*20; i += 128){
        int p = i / 20, k = i % 20;
        float a0 = (k < 19) ? Wfus[(2*p)*19 + k]   : bfus[2*p];
        float a1 = (k < 19) ? Wfus[(2*p+1)*19 + k] : bfus[2*p+1];
        s_fT[i] = make_float2(a0, a1);
    }
    for (int i = tid; i < 64*32; i += 128){
        int o = i >> 5, p = i & 31;
        s_wq2[i] = make_float2(Wq[o*64 + 2*p], Wq[o*64 + 2*p + 1]);
    }
    for (int i = tid; i < 32*64; i += 128){
        int p = i >> 6, o = i & 63;
        s_wv2[i] = make_float2(Wv[o*64 + 2*p], Wv[o*64 + 2*p + 1]);
    }
    for (int i = tid; i < 6*64; i += 128){ int k = i >> 6, o = i & 63; s_wk[i] = Wk[o*6 + k]; }
    if (tid < 64){ s_bq[tid] = bq[tid]; s_bv[tid] = bv[tid]; s_bk[tid] = bk[tid]; }
    __syncthreads();

    const int g   = tid >> 6;
    const int o   = tid & 63;
    const int h   = o >> 4;                 /* head 0..3 */
    const int cl  = o & 15;                 /* lane within head segment */
    const int hb  = o & 16;                 /* warp-local segment base */
    const int bar = g + 1;
    const int ggid    = blockIdx.x*2 + g;
    const int ngroups = gridDim.x*2;
    const unsigned FULL = 0xffffffffu;

    for (int pr = ggid; pr < NP; pr += ngroups){
        const float* sq = seqs + (size_t)pr*54;
        const float* se = ets  + (size_t)pr*36;
        for (int i = o; i < 90; i += 64) s_raw[g][i] = (i < 54) ? sq[i] : se[i-54];
        if (o < 9) s_msk[g][o] = masks[(size_t)pr*9 + o];
        asm volatile("bar.sync %0, 64;" :: "r"(bar) : "memory");
        const float* rg = s_raw[g];

        /* key[o] from self cell (n=4), beta = sum_d key*bq over segment */
        float keyo = s_bk[o];
        #pragma unroll
        for (int k = 0; k < 6; k++) keyo += s_wk[k*64 + o] * rg[24 + k];
        float beta = keyo * s_bq[o];
        #pragma unroll
        for (int mm = 8; mm >= 1; mm >>= 1) beta += __shfl_xor_sync(FULL, beta, mm);

        /* u_h[c] = sum_d key[h,d] Wq[h16+d, c]  (2 c-pairs per lane) */
        ull u0 = 0ULL, u1 = 0ULL;
        #pragma unroll
        for (int d = 0; d < 16; d++){
            float kd = __shfl_sync(FULL, keyo, hb | d);
            ull kd2 = pack2(kd);
            fma2(u0, kd2, *reinterpret_cast<const ull*>(&s_wq2[(h*16 + d)*32 + cl]));
            fma2(u1, kd2, *reinterpret_cast<const ull*>(&s_wq2[(h*16 + d)*32 + cl + 16]));
        }
        s_u[g][h*32 + cl]      = unpk(u0);
        s_u[g][h*32 + cl + 16] = unpk(u1);
        __syncwarp();

        /* wtil[k] = sum_c u[c] Wfus[c,k]; lane cl covers k=cl and k=16+(cl&3) */
        int k2 = 16 + (cl & 3);
        ull t1 = 0ULL, t2 = 0ULL;
        #pragma unroll 8
        for (int p = 0; p < 32; p++){
            ull up = *reinterpret_cast<const ull*>(&s_u[g][h*32 + p]);
            fma2(t1, up, *reinterpret_cast<const ull*>(&s_fT[p*20 + cl]));
            fma2(t2, up, *reinterpret_cast<const ull*>(&s_fT[p*20 + k2]));
        }
        float wt1 = hsum2(t1), wt2 = hsum2(t2);
        float gamma = __shfl_sync(FULL, wt2, hb | 3);       /* k=19: u.bfus */

        float wk_[10];
        #pragma unroll
        for (int k = 0; k < 10; k++) wk_[k] = __shfl_sync(FULL, wt1, hb | k);
        int k10 = 10 + cl;                                  /* valid cl<9 */
        float sA = __shfl_sync(FULL, wt1, hb | (k10 & 15));
        float sB = __shfl_sync(FULL, wt2, hb | ((k10 - 16) & 3));
        float wsel = (k10 < 16) ? sA : sB;

        /* att for slot n=cl (<9): x_n . wtil + gamma + beta, scale, mask */
        float att;
        {
            int n = (cl < 9) ? cl : 8;
            float t = gamma + beta + wsel;
            #pragma unroll
            for (int k = 0; k < 6; k++) t += rg[n*6 + k] * wk_[k];
            #pragma unroll
            for (int j = 0; j < 4; j++) t += rg[54 + n*4 + j] * wk_[6 + j];
            t *= 0.25f;
            att = (cl < 9) ? ((s_msk[g][n] == 0) ? -1e10f : t) : -1e30f;
        }
        /* softmax over 9 inside 16-lane segment */
        float m = att;
        #pragma unroll
        for (int mm = 8; mm >= 1; mm >>= 1) m = fmaxf(m, __shfl_xor_sync(FULL, m, mm));
        float ex = __expf(att - m);
        float ssum = ex;
        #pragma unroll
        for (int mm = 8; mm >= 1; mm >>= 1) ssum += __shfl_xor_sync(FULL, ssum, mm);
        float inv = 1.f / ssum;
        float a[9];
        #pragma unroll
        for (int n = 0; n < 9; n++) a[n] = __shfl_sync(FULL, ex, hb | n) * inv;

        /* xbar[k] = sum_n a[n] x_n[k], k=0..9 (lane k computes, then gather) */
        float xb = 0.f;
        {
            int kx = (cl < 10) ? cl : 9;
            #pragma unroll
            for (int n = 0; n < 9; n++)
                xb += a[n] * ((kx < 6) ? rg[n*6 + kx] : rg[54 + n*4 + (kx - 6)]);
        }
        float xk[10];
        #pragma unroll
        for (int k = 0; k < 10; k++) xk[k] = __shfl_sync(FULL, xb, hb | k);

        /* ebar pairs: Wfus xbar + sum_n a_n Wfus[:,10+n] + bfus */
        ull e0 = 0ULL, e1 = 0ULL;
        #pragma unroll
        for (int k = 0; k < 10; k++){
            ull xk2 = pack2(xk[k]);
            fma2(e0, xk2, *reinterpret_cast<const ull*>(&s_fus[k*64 + 2*cl]));
            fma2(e1, xk2, *reinterpret_cast<const ull*>(&s_fus[k*64 + 2*cl + 32]));
        }
        #pragma unroll
        for (int n = 0; n < 9; n++){
            ull an2 = pack2(a[n]);
            fma2(e0, an2, *reinterpret_cast<const ull*>(&s_fus[(10+n)*64 + 2*cl]));
            fma2(e1, an2, *reinterpret_cast<const ull*>(&s_fus[(10+n)*64 + 2*cl + 32]));
        }
        {
            float2 f0 = unpk(e0), f1 = unpk(e1);
            const float2 b0 = *reinterpret_cast<const float2*>(&s_fus[19*64 + 2*cl]);
            const float2 b1 = *reinterpret_cast<const float2*>(&s_fus[19*64 + 2*cl + 32]);
            s_e[g][h*32 + cl]      = make_float2(f0.x + b0.x, f0.y + b0.y);
            s_e[g][h*32 + cl + 16] = make_float2(f1.x + b1.x, f1.y + b1.y);
        }
        __syncwarp();

        /* ctx[o] = Wv[o,:] . ebar_h + bv[o] */
        ull cacc = 0ULL;
        #pragma unroll 8
        for (int p = 0; p < 32; p++){
            ull ep = *reinterpret_cast<const ull*>(&s_e[g][h*32 + p]);
            fma2(cacc, ep, *reinterpret_cast<const ull*>(&s_wv2[p*64 + o]));
        }
        float ctx = hsum2(cacc) + s_bv[o];

        int b = pr / SEQL, s = pr - b*SEQL;            /* time-major for LSTM */
        g_ctx[((size_t)s*BSZ + b)*ATTD + o] = ctx;
        asm volatile("bar.sync %0, 64;" :: "r"(bar) : "memory");
    }
}

/* ============ kernel 2: xg = ctx @ W_ih^T + (b_ih + b_hh) =============== */
__global__ void __launch_bounds__(128) k_xg(
    const float* __restrict__ Wih, const float* __restrict__ bih, const float* __restrict__ bhh)
{
    __shared__ __align__(16) float4 s_w4[16*128];  /* [kq][jj] 4-k packed, 32KB */
    __shared__ float s_b[128];
    __shared__ __align__(16) float s_c[16*64];     /* 16 ctx rows */
    const int tid = threadIdx.x;
    const int jt  = blockIdx.x & 3;
    const int rb  = blockIdx.x >> 2;               /* 0..221 */
    const int j   = jt*128 + tid;

    for (int i = tid; i < 16*128; i += 128){
        int kq = i >> 7, jj = i & 127, jg = jt*128 + jj;
        s_w4[i] = make_float4(Wih[jg*64 + 4*kq],   Wih[jg*64 + 4*kq+1],
                              Wih[jg*64 + 4*kq+2], Wih[jg*64 + 4*kq+3]);
    }
    s_b[tid] = bih[j] + bhh[j];
    __syncthreads();

    for (int r0 = rb*16; r0 < NP; r0 += 222*16){   /* NP % 16 == 0 */
        for (int i = tid; i < 16*64; i += 128) s_c[i] = g_ctx[(size_t)r0*64 + i];
        __syncthreads();
        ull acc2[16];
        #pragma unroll
        for (int r = 0; r < 16; r++) acc2[r] = 0ULL;
        #pragma unroll 4
        for (int kq = 0; kq < 16; kq++){
            ulonglong2 w = *reinterpret_cast<const ulonglong2*>(&s_w4[kq*128 + tid]);
            #pragma unroll
            for (int r = 0; r < 16; r++){
                ulonglong2 c = *reinterpret_cast<const ulonglong2*>(&s_c[r*64 + 4*kq]);
                fma2(acc2[r], w.x, c.x);
                fma2(acc2[r], w.y, c.y);
            }
        }
        float bj = s_b[tid];
        #pragma unroll
        for (int r = 0; r < 16; r++){
            g_xg[(size_t)(r0+r)*G4 + j] = hsum2(acc2[r]) + bj;
        }
        __syncthreads();
    }
}

/* ============ kernel 3: recurrent LSTM scan + output GEMM (R7 proven) === */
__global__ void __launch_bounds__(512, 2) k_lstm(
    const float* __restrict__ Wout, const float* __restrict__ bout, float* __restrict__ outp)
{
    __shared__ __align__(16) float s_h[8*HIDD];    /* 4 KB  */
    __shared__ __align__(16) float s_g[64*HIDD];   /* 32 KB */
    const int tid = threadIdx.x;
    const int c   = tid & 255;                     /* owns cols c and c+256 */
    const int rh  = tid >> 8;                      /* rows 4rh..4rh+3 */
    const int b0  = blockIdx.x * 8;
    for (int i = tid; i < 8*HIDD; i += 512) s_h[i] = 0.f;
    float creg[2] = {0.f, 0.f};
    __syncthreads();

    const ulonglong2* __restrict__ wp = reinterpret_cast<const ulonglong2*>(g_whh4t);

    for (int s = 0; s < SEQL; s++){
        const float* xgp = g_xg + ((size_t)s*BSZ + b0)*G4;
        float xv0[4], xv1[4];
        #pragma unroll
        for (int r = 0; r < 4; r++){
            int row = rh*4 + r;
            xv0[r] = __ldg(&xgp[(size_t)row*G4 + c]);
            xv1[r] = __ldg(&xgp[(size_t)row*G4 + c + 256]);
        }

        ull acc0[4], acc1[4];
        #pragma unroll
        for (int r = 0; r < 4; r++){ acc0[r] = 0ULL; acc1[r] = 0ULL; }

        #pragma unroll 4
        for (int kq = 0; kq < 32; kq++){
            ulonglong2 w0 = __ldg(&wp[kq*G4 + c]);
            ulonglong2 w1 = __ldg(&wp[kq*G4 + 256 + c]);
            ulonglong2 h[4];
            #pragma unroll
            for (int r = 0; r < 4; r++)
                h[r] = *reinterpret_cast<const ulonglong2*>(&s_h[(rh*4 + r)*HIDD + 4*kq]);
            #pragma unroll
            for (int r = 0; r < 4; r++){
                fma2(acc0[r], w0.x, h[r].x);
                fma2(acc0[r], w0.y, h[r].y);
                fma2(acc1[r], w1.x, h[r].x);
                fma2(acc1[r], w1.y, h[r].y);
            }
        }

        #pragma unroll
        for (int r = 0; r < 4; r++){
            int row = rh*4 + r;
            s_g[row*G4 + c]       = hsum2(acc0[r]) + xv0[r];
            s_g[row*G4 + c + 256] = hsum2(acc1[r]) + xv1[r];
        }
        __syncthreads();
        #pragma unroll
        for (int q = 0; q < 2; q++){                        /* 1024 cells / 512 thr */
            int cell = q*512 + tid;
            int r = cell >> 7, j = cell & 127;
            float ig = sigm(s_g[r*G4 + j]);
            float fg = sigm(s_g[r*G4 + 128 + j]);
            float gg = tanhfast(s_g[r*G4 + 256 + j]);
            float og = sigm(s_g[r*G4 + 384 + j]);
            float cc = fg*creg[q] + ig*gg;
            creg[q]  = cc;
            s_h[r*HIDD + j] = og * tanhfast(cc);
        }
        __syncthreads();
    }

    /* out = h_last @ W_out^T + b_out */
    float* s_wo = s_g;
    for (int i = tid; i < 64*HIDD; i += 512){
        int oo = i & 63, jj = i >> 6;
        s_wo[jj*64 + oo] = Wout[oo*HIDD + jj];
    }
    __syncthreads();
    {
        int r = tid >> 6, oo = tid & 63;
        float acc = __ldg(&bout[oo]);
        #pragma unroll 8
        for (int jj = 0; jj < HIDD; jj++) acc += s_wo[jj*64 + oo] * s_h[r*HIDD + jj];
        outp[(size_t)(b0 + r)*64 + oo] = acc;
    }
}

/* ======================================================================== */
extern "C" void kernel_launch(void* const* d_in, const int* in_sizes, int n_in,
                              void* d_out, int out_size)
{
    const float* seqs = (const float*)d_in[0];
    const float* ets  = (const float*)d_in[1];
    const int*   msk  = (const int*)  d_in[2];
    const float* Wfus = (const float*)d_in[3];
    const float* bfus = (const float*)d_in[4];
    const float* Wk   = (const float*)d_in[5];
    const float* bk   = (const float*)d_in[6];
    const float* Wq   = (const float*)d_in[7];
    const float* bq   = (const float*)d_in[8];
    const float* Wv   = (const float*)d_in[9];
    const float* bv   = (const float*)d_in[10];
    const float* Wih  = (const float*)d_in[11];
    const float* Whh  = (const float*)d_in[12];
    const float* bih  = (const float*)d_in[13];
    const float* bhh  = (const float*)d_in[14];
    const float* Wout = (const float*)d_in[15];
    const float* bout = (const float*)d_in[16];
    float* outp = (float*)d_out;

    k_pack<<<32, 512>>>(Whh);
    k_ctx <<<592, 128>>>(seqs, ets, msk, Wfus, bfus, Wk, bk, Wq, bq, Wv, bv);
    k_xg  <<<888, 128>>>(Wih, bih, bhh);
    k_lstm<<<256, 512>>>(Wout, bout, outp);
}